// round 11
// baseline (speedup 1.0000x reference)
#include <cuda_runtime.h>
#include <cstdint>

// Problem constants
#define NG    128
#define NPTS  8192
#define G     (NG*NG)

// Split config: 64 split-K slabs of KC=128, each in 2 sub-chunks of 64.
// Grid = (2 k-halves) x (64 splits) = 128 CTAs (one wave on 148 SMs).
#define SPL   64
#define KC    128
#define SUB   64

// Device scratch (transposed layouts: [n][j] / [n][k])
__device__ float g_At[NPTS * NG];           // A^T[n][j]
__device__ float g_Bt[NPTS * NG];           // B^T[n][k]
__device__ float g_Part[SPL * 3 * G];       // partials: [s][c][k*128 + j]

// ---------------------------------------------------------------------------
// Kernel 1: separable RBF factors via multiplicative recurrence.
//   w_j = base_j * exp(gv_{j0}*c - 0.5 c^2) * r^(j-j0),  r = exp(+/- h*c)
// 2 __expf per 32-wide segment instead of 32. Thread -> (plane, n, seg).
// ---------------------------------------------------------------------------
__global__ __launch_bounds__(256) void prep_kernel(const float* __restrict__ X) {
    __shared__ float base[128];
    const float h = 4.0f / 127.0f;
    int tid = threadIdx.x;
    if (tid < 128) {
        float gv = -2.0f + h * (float)tid;
        base[tid] = __expf(-0.5f * gv * gv);   // same for both axes (squared)
    }
    __syncthreads();

    int t = blockIdx.x * 256 + tid;            // 0 .. 65535
    int plane = t >> 15;                       // 2 planes x 8192 n x 4 segs
    int rem   = t & 32767;
    int n   = rem >> 2;
    int j0  = (rem & 3) * 32;

    float c = X[n * 2 + plane];
    float gv0 = plane ? (2.0f - h * (float)j0) : (-2.0f + h * (float)j0);
    float r = __expf(plane ? -h * c : h * c);
    float p = __expf(gv0 * c - 0.5f * c * c);

    float* dst = (plane ? g_Bt : g_At) + n * 128 + j0;
    #pragma unroll
    for (int q = 0; q < 8; q++) {
        float4 buf;
        buf.x = p * base[j0 + q * 4 + 0]; p *= r;
        buf.y = p * base[j0 + q * 4 + 1]; p *= r;
        buf.z = p * base[j0 + q * 4 + 2]; p *= r;
        buf.w = p * base[j0 + q * 4 + 3]; p *= r;
        *(float4*)(dst + q * 4) = buf;
    }
}

// ---------------------------------------------------------------------------
// Packed fp32x2 helpers
// ---------------------------------------------------------------------------
__device__ __forceinline__ unsigned long long pk2(float lo, float hi) {
    unsigned long long r;
    asm("mov.b64 %0, {%1, %2};" : "=l"(r) : "f"(lo), "f"(hi));
    return r;
}
__device__ __forceinline__ void upk2(unsigned long long v, float& lo, float& hi) {
    asm("mov.b64 {%0, %1}, %2;" : "=f"(lo), "=f"(hi) : "l"(v));
}
__device__ __forceinline__ void fma2(unsigned long long& d,
                                     unsigned long long a, unsigned long long b) {
    asm("fma.rn.f32x2 %0, %1, %2, %0;" : "+l"(d) : "l"(a), "l"(b));
}

// ---------------------------------------------------------------------------
// Kernel 2: split-K contraction, 512 threads/CTA (4 warps/SMSP).
// jg = lane (A loads conflict-free), kg = warp id (T loads are broadcasts).
// Thread tile: 4 j (stride 32) x 2 k-pairs x 3 c = 24 packed accumulators.
// ---------------------------------------------------------------------------
__global__ __launch_bounds__(512, 1) void gemm_kernel(const float* __restrict__ Y) {
    extern __shared__ float smem[];
    float* As = smem;                    // [SUB][128]   32 KB
    float* Ts = smem + SUB * 128;        // [3][SUB][64] 48 KB

    const int kh  = blockIdx.x;
    const int s   = blockIdx.y;
    const int tid = threadIdx.x;
    const int jg  = tid & 31;            // lane id: j = jg + 32*i
    const int k0  = (tid >> 5) * 4;      // warp id: k = k0 + {0..3}

    unsigned long long acc[4][2][3];
    #pragma unroll
    for (int i = 0; i < 4; i++)
        #pragma unroll
        for (int p = 0; p < 2; p++)
            #pragma unroll
            for (int c = 0; c < 3; c++)
                acc[i][p][c] = 0ull;

    for (int sub = 0; sub < 2; sub++) {
        const int n0 = s * KC + sub * SUB;
        __syncthreads();

        const float4* srcA = (const float4*)(g_At + n0 * 128);
        #pragma unroll
        for (int i = tid; i < SUB * 32; i += 512)
            ((float4*)As)[i] = srcA[i];

        #pragma unroll
        for (int i = tid; i < SUB * 16; i += 512) {
            int n = i >> 4, q = i & 15;
            float4 b = *(const float4*)(g_Bt + (n0 + n) * 128 + kh * 64 + q * 4);
            float2 e = ((const float2*)Y)[n0 + n];
            *(float4*)&Ts[(0 * SUB + n) * 64 + q * 4] = b;
            *(float4*)&Ts[(1 * SUB + n) * 64 + q * 4] =
                make_float4(b.x * e.x, b.y * e.x, b.z * e.x, b.w * e.x);
            *(float4*)&Ts[(2 * SUB + n) * 64 + q * 4] =
                make_float4(b.x * e.y, b.y * e.y, b.z * e.y, b.w * e.y);
        }
        __syncthreads();

        #pragma unroll 4
        for (int n = 0; n < SUB; n++) {
            unsigned long long t2[3][2];
            #pragma unroll
            for (int c = 0; c < 3; c++)
                #pragma unroll
                for (int p = 0; p < 2; p++)
                    t2[c][p] = *(const unsigned long long*)
                               &Ts[(c * SUB + n) * 64 + k0 + p * 2];

            const float* Arow = As + n * 128 + jg;
            #pragma unroll
            for (int i = 0; i < 4; i++) {
                float a = Arow[32 * i];
                unsigned long long a2 = pk2(a, a);
                #pragma unroll
                for (int p = 0; p < 2; p++) {
                    fma2(acc[i][p][0], a2, t2[0][p]);
                    fma2(acc[i][p][1], a2, t2[1][p]);
                    fma2(acc[i][p][2], a2, t2[2][p]);
                }
            }
        }
    }

    // Epilogue: partials, layout [s][c][k*128 + j]; lanes -> consecutive j.
    float* P = g_Part + (size_t)s * 3 * G;
    #pragma unroll
    for (int i = 0; i < 4; i++) {
        int j = jg + 32 * i;
        #pragma unroll
        for (int p = 0; p < 2; p++) {
            int k = kh * 64 + k0 + p * 2;
            #pragma unroll
            for (int c = 0; c < 3; c++) {
                float lo, hi;
                upk2(acc[i][p][c], lo, hi);
                P[c * G + k * 128 + j]       = lo;
                P[c * G + (k + 1) * 128 + j] = hi;
            }
        }
    }
}

// ---------------------------------------------------------------------------
// Kernel 3: reduce + normalize. 2 threads per grid point (32 splits each),
// shfl combine -> 128 CTAs, doubled MLP.
// ---------------------------------------------------------------------------
__global__ __launch_bounds__(256) void reduce_kernel(float* __restrict__ out) {
    int t  = blockIdx.x * 256 + threadIdx.x;   // 0..32767
    int g  = t >> 1;
    int sh = t & 1;
    float s0 = 0.f, s1 = 0.f, s2 = 0.f;
    const float* P = g_Part + (size_t)(sh * 32) * 3 * G;
    #pragma unroll 8
    for (int s = 0; s < 32; s++, P += 3 * G) {
        s0 += P[g];
        s1 += P[G + g];
        s2 += P[2 * G + g];
    }
    s0 += __shfl_xor_sync(0xFFFFFFFFu, s0, 1);
    s1 += __shfl_xor_sync(0xFFFFFFFFu, s1, 1);
    s2 += __shfl_xor_sync(0xFFFFFFFFu, s2, 1);
    if (sh == 0) {
        out[g]         = s0;
        out[G + g]     = s1 / s0;
        out[2 * G + g] = s2 / s0;
    }
}

// ---------------------------------------------------------------------------
extern "C" void kernel_launch(void* const* d_in, const int* in_sizes, int n_in,
                              void* d_out, int out_size) {
    const float* X = (const float*)d_in[0];
    const float* Y = (const float*)d_in[1];
    float* out = (float*)d_out;

    const int smem_bytes = (SUB * 128 + 3 * SUB * 64) * sizeof(float);  // 80 KB
    cudaFuncSetAttribute(gemm_kernel, cudaFuncAttributeMaxDynamicSharedMemorySize,
                         smem_bytes);

    prep_kernel<<<256, 256>>>(X);
    gemm_kernel<<<dim3(2, SPL), 512, smem_bytes>>>(Y);
    reduce_kernel<<<128, 256>>>(out);
}